// round 1
// baseline (speedup 1.0000x reference)
#include <cuda_runtime.h>
#include <math.h>

#define SEQ 2048
#define HID 2048
#define NHEAD 32
#define HDIM 64
#define ISZ 8192
#define NLAYER 2

// ---------------- scratch (static device arrays; no allocation) ----------------
__device__ float g_x  [SEQ * HID];   // residual stream
__device__ float g_h  [SEQ * HID];   // layernorm output
__device__ float g_q  [SEQ * HID];
__device__ float g_k  [SEQ * HID];
__device__ float g_v  [SEQ * HID];
__device__ float g_ctx[SEQ * HID];
__device__ float g_mid[SEQ * ISZ];   // MLP intermediate

// ---------------- copy ----------------
__global__ void copy_kernel(const float4* __restrict__ in, float4* __restrict__ out, int n4) {
    int i = blockIdx.x * 256 + threadIdx.x;
    if (i < n4) out[i] = in[i];
}

// ---------------- layernorm (center=false beta, scale by gamma) ----------------
__global__ void __launch_bounds__(256) ln_kernel(const float* __restrict__ x,
                                                 const float* __restrict__ gamma,
                                                 float* __restrict__ out) {
    __shared__ float sh[18];
    int row = blockIdx.x;
    const float* xr = x + row * HID;
    float s = 0.f, s2 = 0.f;
    for (int i = threadIdx.x; i < HID; i += 256) {
        float v = xr[i];
        s += v; s2 += v * v;
    }
    #pragma unroll
    for (int o = 16; o; o >>= 1) {
        s  += __shfl_xor_sync(0xFFFFFFFFu, s,  o);
        s2 += __shfl_xor_sync(0xFFFFFFFFu, s2, o);
    }
    int w = threadIdx.x >> 5, lane = threadIdx.x & 31;
    if (lane == 0) { sh[w] = s; sh[8 + w] = s2; }
    __syncthreads();
    if (threadIdx.x < 32) {
        s  = (threadIdx.x < 8) ? sh[threadIdx.x]     : 0.f;
        s2 = (threadIdx.x < 8) ? sh[8 + threadIdx.x] : 0.f;
        #pragma unroll
        for (int o = 4; o; o >>= 1) {
            s  += __shfl_xor_sync(0xFFFFFFFFu, s,  o);
            s2 += __shfl_xor_sync(0xFFFFFFFFu, s2, o);
        }
        if (threadIdx.x == 0) {
            float mu = s * (1.0f / HID);
            float var = s2 * (1.0f / HID) - mu * mu;
            sh[16] = mu;
            sh[17] = rsqrtf(var + 1e-5f);
        }
    }
    __syncthreads();
    float mu = sh[16], inv = sh[17];
    for (int i = threadIdx.x; i < HID; i += 256)
        out[row * HID + i] = (xr[i] - mu) * inv * gamma[i];
}

// ---------------- SGEMM: C[M,N] = A[M,K] @ B[K,N]  (+epilogue) ----------------
// MODE 0: plain
// MODE 1: C = A@B + bias[c] + res[r,c]
// MODE 2: C = gelu_tanh(A@B)
template <int MODE>
__global__ void __launch_bounds__(256) sgemm_kernel(
    const float* __restrict__ A, const float* __restrict__ B,
    const float* __restrict__ bias, const float* __restrict__ res,
    float* __restrict__ C, int M, int N, int K)
{
    constexpr int BM = 128, BN = 128, BK = 16;
    __shared__ float As[BK][BM + 4];
    __shared__ float Bs[BK][BN];

    int tid = threadIdx.x;
    int tx = tid & 15, ty = tid >> 4;
    const int row0 = blockIdx.y * BM, col0 = blockIdx.x * BN;

    float acc[8][8];
    #pragma unroll
    for (int i = 0; i < 8; i++)
        #pragma unroll
        for (int j = 0; j < 8; j++) acc[i][j] = 0.f;

    const float* Ag = A + (long)row0 * K;
    const float* Bg = B + col0;

    for (int k0 = 0; k0 < K; k0 += BK) {
        #pragma unroll
        for (int u = 0; u < 2; u++) {
            int f = tid + u * 256;          // [0,512)
            int ar = f >> 2, ac4 = f & 3;   // A: 128 rows x 4 float4
            float4 av = *(const float4*)(Ag + (long)ar * K + k0 + ac4 * 4);
            As[ac4 * 4 + 0][ar] = av.x;
            As[ac4 * 4 + 1][ar] = av.y;
            As[ac4 * 4 + 2][ar] = av.z;
            As[ac4 * 4 + 3][ar] = av.w;
            int br = f >> 5, bc = (f & 31) * 4;  // B: 16 rows x 32 float4
            *(float4*)(&Bs[br][bc]) = *(const float4*)(Bg + (long)(k0 + br) * N + bc);
        }
        __syncthreads();
        #pragma unroll
        for (int kk = 0; kk < BK; kk++) {
            float4 a0 = *(const float4*)(&As[kk][ty * 8]);
            float4 a1 = *(const float4*)(&As[kk][ty * 8 + 4]);
            float4 b0 = *(const float4*)(&Bs[kk][tx * 8]);
            float4 b1 = *(const float4*)(&Bs[kk][tx * 8 + 4]);
            float a[8] = {a0.x, a0.y, a0.z, a0.w, a1.x, a1.y, a1.z, a1.w};
            float b[8] = {b0.x, b0.y, b0.z, b0.w, b1.x, b1.y, b1.z, b1.w};
            #pragma unroll
            for (int i = 0; i < 8; i++)
                #pragma unroll
                for (int j = 0; j < 8; j++) acc[i][j] += a[i] * b[j];
        }
        __syncthreads();
    }

    #pragma unroll
    for (int i = 0; i < 8; i++) {
        int r = row0 + ty * 8 + i;
        #pragma unroll
        for (int j = 0; j < 8; j++) {
            int c = col0 + tx * 8 + j;
            float v = acc[i][j];
            if (MODE == 1) v += bias[c] + res[(long)r * N + c];
            if (MODE == 2) {
                float t = 0.7978845608028654f * v * (1.0f + 0.044715f * v * v);
                v = 0.5f * v * (1.0f + tanhf(t));
            }
            C[(long)r * N + c] = v;
        }
    }
}

// ---------------- flash attention (fp32, causal) ----------------
// grid: (S/BQ, NHEAD), 256 threads. Each thread owns query row r = tid>>2 and
// 16 output dims starting at (tid&3)*16; 4 threads/row redundantly track m,l.
__global__ void __launch_bounds__(256) attn_kernel(
    const float* __restrict__ Q, const float* __restrict__ K,
    const float* __restrict__ V, float* __restrict__ O)
{
    constexpr int BQ = 64, BK = 32;
    __shared__ float Qs[BQ][HDIM + 1];
    __shared__ float Ks[BK][HDIM + 1];
    __shared__ float Vs[BK][HDIM + 1];
    __shared__ float Ss[BQ][BK + 1];

    int qb = blockIdx.x, h = blockIdx.y;
    int tid = threadIdx.x;
    int r = tid >> 2, g = tid & 3;
    int qg = qb * BQ + r;
    const float scale = 0.125f;  // 1/sqrt(64)

    // load Q tile [64, 64]
    for (int f = tid; f < BQ * 16; f += 256) {
        int rr = f >> 4, c4 = f & 15;
        float4 v4 = *(const float4*)(Q + (long)(qb * BQ + rr) * HID + h * HDIM + c4 * 4);
        Qs[rr][c4 * 4 + 0] = v4.x; Qs[rr][c4 * 4 + 1] = v4.y;
        Qs[rr][c4 * 4 + 2] = v4.z; Qs[rr][c4 * 4 + 3] = v4.w;
    }

    float m_i = -1e30f, l_i = 0.f;
    float o[16];
    #pragma unroll
    for (int i = 0; i < 16; i++) o[i] = 0.f;

    int nkt = (qb + 1) * (BQ / BK);  // causal: tiles covering keys [0, qb*64+64)

    for (int kt = 0; kt < nkt; kt++) {
        __syncthreads();  // prior-iteration reads done (and Qs ready on iter 0)
        for (int f = tid; f < BK * 16; f += 256) {
            int rr = f >> 4, c4 = f & 15;
            long base = (long)(kt * BK + rr) * HID + h * HDIM + c4 * 4;
            float4 kv = *(const float4*)(K + base);
            Ks[rr][c4 * 4 + 0] = kv.x; Ks[rr][c4 * 4 + 1] = kv.y;
            Ks[rr][c4 * 4 + 2] = kv.z; Ks[rr][c4 * 4 + 3] = kv.w;
            float4 vv = *(const float4*)(V + base);
            Vs[rr][c4 * 4 + 0] = vv.x; Vs[rr][c4 * 4 + 1] = vv.y;
            Vs[rr][c4 * 4 + 2] = vv.z; Vs[rr][c4 * 4 + 3] = vv.w;
        }
        __syncthreads();

        // scores: thread computes 8 keys k = g*8 .. g*8+7 for its row r
        float sacc[8];
        #pragma unroll
        for (int kk = 0; kk < 8; kk++) sacc[kk] = 0.f;
        #pragma unroll 4
        for (int d = 0; d < HDIM; d++) {
            float qv = Qs[r][d];
            #pragma unroll
            for (int kk = 0; kk < 8; kk++) sacc[kk] += qv * Ks[g * 8 + kk][d];
        }
        #pragma unroll
        for (int kk = 0; kk < 8; kk++) {
            int k = g * 8 + kk;
            int kg = kt * BK + k;
            float v = sacc[kk] * scale;
            if (kg > qg) v = -1e30f;
            Ss[r][k] = v;
        }
        __syncthreads();

        // online softmax + P@V for this row / 16 owned dims
        float m_new = m_i;
        #pragma unroll
        for (int k = 0; k < BK; k++) m_new = fmaxf(m_new, Ss[r][k]);
        float alpha = __expf(m_i - m_new);
        l_i *= alpha;
        #pragma unroll
        for (int i = 0; i < 16; i++) o[i] *= alpha;
        #pragma unroll 4
        for (int k = 0; k < BK; k++) {
            float p = __expf(Ss[r][k] - m_new);
            l_i += p;
            const float* vrow = &Vs[k][g * 16];
            #pragma unroll
            for (int i = 0; i < 16; i++) o[i] += p * vrow[i];
        }
        m_i = m_new;
    }

    float inv = 1.0f / l_i;
    long obase = (long)qg * HID + h * HDIM + g * 16;
    #pragma unroll
    for (int i = 0; i < 16; i++) O[obase + i] = o[i] * inv;
}

// ---------------- orchestration ----------------
extern "C" void kernel_launch(void* const* d_in, const int* in_sizes, int n_in,
                              void* d_out, int out_size) {
    const float* emb = (const float*)d_in[0];
    // d_in[1] = attention_mask (always causal tril) — masked analytically, ignored
    const float* Wq = (const float*)d_in[2];
    const float* Wk = (const float*)d_in[3];
    const float* Wv = (const float*)d_in[4];
    const float* Wo = (const float*)d_in[5];
    const float* bo = (const float*)d_in[6];
    const float* W1 = (const float*)d_in[7];
    const float* W2 = (const float*)d_in[8];
    const float* b2 = (const float*)d_in[9];
    const float* g1 = (const float*)d_in[10];
    const float* g2 = (const float*)d_in[11];
    const float* gf = (const float*)d_in[12];
    float* out = (float*)d_out;

    float *px, *ph, *pq, *pk, *pv, *pctx, *pmid;
    cudaGetSymbolAddress((void**)&px,   g_x);
    cudaGetSymbolAddress((void**)&ph,   g_h);
    cudaGetSymbolAddress((void**)&pq,   g_q);
    cudaGetSymbolAddress((void**)&pk,   g_k);
    cudaGetSymbolAddress((void**)&pv,   g_v);
    cudaGetSymbolAddress((void**)&pctx, g_ctx);
    cudaGetSymbolAddress((void**)&pmid, g_mid);

    // x = inputs_embeds
    {
        int n4 = SEQ * HID / 4;
        copy_kernel<<<(n4 + 255) / 256, 256>>>((const float4*)emb, (float4*)px, n4);
    }

    dim3 gHH(HID / 128, SEQ / 128);   // N=2048 GEMMs
    dim3 gHI(ISZ / 128, SEQ / 128);   // N=8192 GEMM (MLP up)
    dim3 gAttn(SEQ / 64, NHEAD);

    for (int l = 0; l < NLAYER; l++) {
        const float* wq = Wq + (long)l * HID * HID;
        const float* wk = Wk + (long)l * HID * HID;
        const float* wv = Wv + (long)l * HID * HID;
        const float* wo = Wo + (long)l * HID * HID;
        const float* w1 = W1 + (long)l * HID * ISZ;
        const float* w2 = W2 + (long)l * ISZ * HID;

        // attention block
        ln_kernel<<<SEQ, 256>>>(px, g1 + l * HID, ph);
        sgemm_kernel<0><<<gHH, 256>>>(ph, wq, nullptr, nullptr, pq, SEQ, HID, HID);
        sgemm_kernel<0><<<gHH, 256>>>(ph, wk, nullptr, nullptr, pk, SEQ, HID, HID);
        sgemm_kernel<0><<<gHH, 256>>>(ph, wv, nullptr, nullptr, pv, SEQ, HID, HID);
        attn_kernel<<<gAttn, 256>>>(pq, pk, pv, pctx);
        // x = x + ctx @ Wo + bo
        sgemm_kernel<1><<<gHH, 256>>>(pctx, wo, bo + l * HID, px, px, SEQ, HID, HID);

        // MLP block
        ln_kernel<<<SEQ, 256>>>(px, g2 + l * HID, ph);
        sgemm_kernel<2><<<gHI, 256>>>(ph, w1, nullptr, nullptr, pmid, SEQ, ISZ, HID);
        // x = x + mid @ W2 + b2
        sgemm_kernel<1><<<gHH, 256>>>(pmid, w2, b2 + l * HID, px, px, SEQ, HID, ISZ);
    }

    ln_kernel<<<SEQ, 256>>>(px, gf, out);
}

// round 3
// speedup vs baseline: 1.2104x; 1.2104x over previous
#include <cuda_runtime.h>
#include <cuda_bf16.h>
#include <math.h>
#include <stdint.h>

#define SEQ 2048
#define HID 2048
#define NHEAD 32
#define HDIM 64
#define ISZ 8192
#define NLAYER 2

// ======================= scratch (static device arrays) =======================
__device__ float g_x  [SEQ * HID];                 // residual stream (fp32)
__device__ float g_q  [SEQ * HID];
__device__ float g_k  [SEQ * HID];
__device__ float g_v  [SEQ * HID];
__device__ __nv_bfloat16 g_hh [SEQ * HID];         // LN out hi/lo
__device__ __nv_bfloat16 g_hl [SEQ * HID];
__device__ __nv_bfloat16 g_ctxh[SEQ * HID];        // attn out hi/lo
__device__ __nv_bfloat16 g_ctxl[SEQ * HID];
__device__ __nv_bfloat16 g_midh[SEQ * ISZ];        // MLP mid hi/lo
__device__ __nv_bfloat16 g_midl[SEQ * ISZ];
// transposed + split weights: Wt[N][K]
__device__ __nv_bfloat16 g_wqt_h[NLAYER * HID * HID], g_wqt_l[NLAYER * HID * HID];
__device__ __nv_bfloat16 g_wkt_h[NLAYER * HID * HID], g_wkt_l[NLAYER * HID * HID];
__device__ __nv_bfloat16 g_wvt_h[NLAYER * HID * HID], g_wvt_l[NLAYER * HID * HID];
__device__ __nv_bfloat16 g_wot_h[NLAYER * HID * HID], g_wot_l[NLAYER * HID * HID];
__device__ __nv_bfloat16 g_w1t_h[NLAYER * HID * ISZ], g_w1t_l[NLAYER * HID * ISZ];
__device__ __nv_bfloat16 g_w2t_h[NLAYER * ISZ * HID], g_w2t_l[NLAYER * ISZ * HID];

// ======================= PTX helpers (baseline ISA only: sm_80-era) =======================
__device__ __forceinline__ uint32_t smem_u32(const void* p) {
    uint32_t a;
    asm("{ .reg .u64 t; cvta.to.shared.u64 t, %1; cvt.u32.u64 %0, t; }" : "=r"(a) : "l"(p));
    return a;
}
__device__ __forceinline__ void cp16(uint32_t dst, const void* src) {
    asm volatile("cp.async.cg.shared.global [%0], [%1], 16;" :: "r"(dst), "l"(src));
}
__device__ __forceinline__ void cp_commit() {
    asm volatile("cp.async.commit_group;" ::: "memory");
}
template <int N>
__device__ __forceinline__ void cp_wait() {
    asm volatile("cp.async.wait_group %0;" :: "n"(N) : "memory");
}
__device__ __forceinline__ void ldmx4(uint32_t* r, uint32_t addr) {
    asm volatile("ldmatrix.sync.aligned.m8n8.x4.shared.b16 {%0,%1,%2,%3}, [%4];"
                 : "=r"(r[0]), "=r"(r[1]), "=r"(r[2]), "=r"(r[3]) : "r"(addr));
}
__device__ __forceinline__ void mma16816(float* d, const uint32_t* a, const uint32_t* b) {
    asm volatile("mma.sync.aligned.m16n8k16.row.col.f32.bf16.bf16.f32 "
                 "{%0,%1,%2,%3}, {%4,%5,%6,%7}, {%8,%9}, {%0,%1,%2,%3};"
                 : "+f"(d[0]), "+f"(d[1]), "+f"(d[2]), "+f"(d[3])
                 : "r"(a[0]), "r"(a[1]), "r"(a[2]), "r"(a[3]), "r"(b[0]), "r"(b[1]));
}

// ======================= small kernels =======================
__global__ void copy_kernel(const float4* __restrict__ in, float4* __restrict__ out, int n4) {
    int i = blockIdx.x * 256 + threadIdx.x;
    if (i < n4) out[i] = in[i];
}

__device__ __forceinline__ float gelu_tanh(float v) {
    float t = 0.7978845608028654f * v * (1.0f + 0.044715f * v * v);
    return 0.5f * v * (1.0f + tanhf(t));
}

// layernorm; SPLIT=1 -> write bf16 hi/lo, SPLIT=0 -> write fp32
template <int SPLIT>
__global__ void __launch_bounds__(256) ln_kernel(const float* __restrict__ x,
                                                 const float* __restrict__ gamma,
                                                 float* __restrict__ outf,
                                                 __nv_bfloat16* __restrict__ oh,
                                                 __nv_bfloat16* __restrict__ ol) {
    __shared__ float sh[18];
    int row = blockIdx.x;
    const float* xr = x + (long)row * HID;
    float s = 0.f, s2 = 0.f;
    for (int i = threadIdx.x; i < HID; i += 256) {
        float v = xr[i];
        s += v; s2 += v * v;
    }
    #pragma unroll
    for (int o = 16; o; o >>= 1) {
        s  += __shfl_xor_sync(0xFFFFFFFFu, s,  o);
        s2 += __shfl_xor_sync(0xFFFFFFFFu, s2, o);
    }
    int w = threadIdx.x >> 5, lane = threadIdx.x & 31;
    if (lane == 0) { sh[w] = s; sh[8 + w] = s2; }
    __syncthreads();
    if (threadIdx.x < 32) {
        s  = (threadIdx.x < 8) ? sh[threadIdx.x]     : 0.f;
        s2 = (threadIdx.x < 8) ? sh[8 + threadIdx.x] : 0.f;
        #pragma unroll
        for (int o = 4; o; o >>= 1) {
            s  += __shfl_xor_sync(0xFFFFFFFFu, s,  o);
            s2 += __shfl_xor_sync(0xFFFFFFFFu, s2, o);
        }
        if (threadIdx.x == 0) {
            float mu = s * (1.0f / HID);
            float var = s2 * (1.0f / HID) - mu * mu;
            sh[16] = mu;
            sh[17] = rsqrtf(var + 1e-5f);
        }
    }
    __syncthreads();
    float mu = sh[16], inv = sh[17];
    for (int i = threadIdx.x; i < HID; i += 256) {
        float v = (xr[i] - mu) * inv * gamma[i];
        if (SPLIT) {
            __nv_bfloat16 h = __float2bfloat16(v);
            oh[(long)row * HID + i] = h;
            ol[(long)row * HID + i] = __float2bfloat16(v - __bfloat162float(h));
        } else {
            outf[(long)row * HID + i] = v;
        }
    }
}

// weight transpose + split: W[K,N] fp32 -> Th/Tl[N,K] bf16
__global__ void __launch_bounds__(256) wsplit_kernel(const float* __restrict__ W,
                                                     __nv_bfloat16* __restrict__ Th,
                                                     __nv_bfloat16* __restrict__ Tl,
                                                     int K, int N) {
    __shared__ float t[32][33];
    int bx = blockIdx.x * 32, by = blockIdx.y * 32;
    int tx = threadIdx.x, ty = threadIdx.y;
    #pragma unroll
    for (int i = 0; i < 4; i++)
        t[ty + i * 8][tx] = W[(long)(by + ty + i * 8) * N + bx + tx];
    __syncthreads();
    #pragma unroll
    for (int i = 0; i < 4; i++) {
        float v = t[tx][ty + i * 8];
        __nv_bfloat16 h = __float2bfloat16(v);
        long o = (long)(bx + ty + i * 8) * K + by + tx;
        Th[o] = h;
        Tl[o] = __float2bfloat16(v - __bfloat162float(h));
    }
}

// ======================= mma.sync split-bf16 GEMM =======================
// C[M,N] = (Ah+Al)[M,K] @ (Bh+Bl)^T  with Bt stored [N,K] row-major.
// Tiles: BM=128, BN=128, BK=32. 8 warps, warp tile 64x32.
// Smem per stage: A[128 rows][128B] where each 128B row = hi k0..31 (64B) | lo k0..31 (64B),
// 16B chunks XOR-swizzled: phys_chunk = c ^ (row&7)  -> conflict-free ldmatrix + cp.async.
// MODE 0: Cf = AB  (fp32)
// MODE 1: Cf = AB + bias + res (fp32; res may alias Cf)
// MODE 2: Ch/Cl = split(gelu(AB))
#define STAGE_BYTES 32768          // 16KB A + 16KB B
#define GSM_TOTAL   (2 * STAGE_BYTES)

__device__ __forceinline__ void load_half_tile(uint32_t sbase,
                                               const __nv_bfloat16* __restrict__ Ph,
                                               const __nv_bfloat16* __restrict__ Pl,
                                               int K, long k0, int tid) {
    // 128 rows x 8 chunks(16B) : chunks 0-3 = hi, 4-7 = lo
    #pragma unroll
    for (int i = 0; i < 4; i++) {
        int idx = tid + i * 256;
        int row = idx >> 3, c = idx & 7;
        const __nv_bfloat16* src = (c < 4 ? Ph : Pl) + (long)row * K + k0 + (c & 3) * 8;
        uint32_t dst = sbase + row * 128 + ((c ^ (row & 7)) << 4);
        cp16(dst, src);
    }
}

template <int MODE>
__global__ void __launch_bounds__(256) gemm_mma_kernel(
    const __nv_bfloat16* __restrict__ Ah, const __nv_bfloat16* __restrict__ Al,
    const __nv_bfloat16* __restrict__ Bh, const __nv_bfloat16* __restrict__ Bl,
    const float* __restrict__ bias, const float* res,
    float* Cf, __nv_bfloat16* __restrict__ Ch, __nv_bfloat16* __restrict__ Cl,
    int M, int N, int K)
{
    extern __shared__ char smem[];
    uint32_t sb = smem_u32(smem);
    int tid = threadIdx.x;
    int wid = tid >> 5, lane = tid & 31;
    int warp_m = wid >> 2, warp_n = wid & 3;       // 2 x 4 warps
    int row0 = blockIdx.y * 128, col0 = blockIdx.x * 128;
    int m0 = warp_m * 64, n0 = warp_n * 32;

    const __nv_bfloat16* pAh = Ah + (long)row0 * K;
    const __nv_bfloat16* pAl = Al + (long)row0 * K;
    const __nv_bfloat16* pBh = Bh + (long)col0 * K;
    const __nv_bfloat16* pBl = Bl + (long)col0 * K;

    float acc[4][4][4];
    #pragma unroll
    for (int i = 0; i < 4; i++)
        #pragma unroll
        for (int j = 0; j < 4; j++)
            #pragma unroll
            for (int q = 0; q < 4; q++) acc[i][j][q] = 0.f;

    // ldmatrix per-lane geometry
    int grp = lane >> 3, lr = lane & 7;
    int rowA = m0 + (grp & 1) * 8 + lr;            // + mt*16
    int ccA  = grp >> 1;                           // + ks*2 (+4 for lo)
    int rowB = n0 + (grp >> 1) * 8 + lr;           // + ntp*16
    int ccB  = grp & 1;                            // + ks*2 (+4 for lo)
    int xA = rowA & 7, xB = rowB & 7;              // invariant under +16

    int nc = K / 32;
    load_half_tile(sb,                 pAh, pAl, K, 0, tid);
    load_half_tile(sb + 16384,         pBh, pBl, K, 0, tid);
    cp_commit();
    load_half_tile(sb + STAGE_BYTES,         pAh, pAl, K, 32, tid);
    load_half_tile(sb + STAGE_BYTES + 16384, pBh, pBl, K, 32, tid);
    cp_commit();

    for (int c = 0; c < nc; c++) {
        cp_wait<1>();
        __syncthreads();
        uint32_t sA = sb + (c & 1) * STAGE_BYTES;
        uint32_t sB = sA + 16384;

        #pragma unroll
        for (int ks = 0; ks < 2; ks++) {
            uint32_t afh[4][4], afl[4][4], bfh[2][4], bfl[2][4];
            #pragma unroll
            for (int mt = 0; mt < 4; mt++) {
                uint32_t base = sA + (rowA + mt * 16) * 128;
                ldmx4(afh[mt], base + (((ks * 2 + ccA)     ^ xA) << 4));
                ldmx4(afl[mt], base + (((ks * 2 + ccA + 4) ^ xA) << 4));
            }
            #pragma unroll
            for (int np = 0; np < 2; np++) {
                uint32_t base = sB + (rowB + np * 16) * 128;
                ldmx4(bfh[np], base + (((ks * 2 + ccB)     ^ xB) << 4));
                ldmx4(bfl[np], base + (((ks * 2 + ccB + 4) ^ xB) << 4));
            }
            #pragma unroll
            for (int mt = 0; mt < 4; mt++)
                #pragma unroll
                for (int nt = 0; nt < 4; nt++) {
                    const uint32_t* bh = &bfh[nt >> 1][(nt & 1) * 2];
                    const uint32_t* bl = &bfl[nt >> 1][(nt & 1) * 2];
                    mma16816(acc[mt][nt], afh[mt], bh);
                    mma16816(acc[mt][nt], afh[mt], bl);
                    mma16816(acc[mt][nt], afl[mt], bh);
                }
        }
        __syncthreads();
        if (c + 2 < nc) {
            uint32_t st = sb + (c & 1) * STAGE_BYTES;
            long k0 = (long)(c + 2) * 32;
            load_half_tile(st,         pAh, pAl, K, k0, tid);
            load_half_tile(st + 16384, pBh, pBl, K, k0, tid);
        }
        cp_commit();
    }

    // ---------------- epilogue (direct from fragments) ----------------
    int r = lane >> 2, c2 = (lane & 3) * 2;
    #pragma unroll
    for (int mt = 0; mt < 4; mt++) {
        #pragma unroll
        for (int nt = 0; nt < 4; nt++) {
            long gr = row0 + m0 + mt * 16 + r;
            long gc = col0 + n0 + nt * 8 + c2;
            #pragma unroll
            for (int hrow = 0; hrow < 2; hrow++) {
                long grr = gr + hrow * 8;
                float v0 = acc[mt][nt][hrow * 2 + 0];
                float v1 = acc[mt][nt][hrow * 2 + 1];
                if (MODE == 0) {
                    *(float2*)(Cf + grr * N + gc) = make_float2(v0, v1);
                } else if (MODE == 1) {
                    float2 b = *(const float2*)(bias + gc);
                    float2 rr = *(const float2*)(res + grr * N + gc);
                    *(float2*)(Cf + grr * N + gc) = make_float2(v0 + b.x + rr.x, v1 + b.y + rr.y);
                } else {
                    float g0 = gelu_tanh(v0), g1 = gelu_tanh(v1);
                    __nv_bfloat16 h0 = __float2bfloat16(g0);
                    __nv_bfloat16 h1 = __float2bfloat16(g1);
                    __nv_bfloat162 hp; hp.x = h0; hp.y = h1;
                    __nv_bfloat162 lp;
                    lp.x = __float2bfloat16(g0 - __bfloat162float(h0));
                    lp.y = __float2bfloat16(g1 - __bfloat162float(h1));
                    *(__nv_bfloat162*)(Ch + grr * N + gc) = hp;
                    *(__nv_bfloat162*)(Cl + grr * N + gc) = lp;
                }
            }
        }
    }
}

// ======================= flash attention (fp32, causal, float4) =======================
__global__ void __launch_bounds__(256) attn_kernel(
    const float* __restrict__ Q, const float* __restrict__ K,
    const float* __restrict__ V,
    __nv_bfloat16* __restrict__ Oh, __nv_bfloat16* __restrict__ Ol)
{
    constexpr int BQ = 64, BK = 32;
    __shared__ float Qs[BQ][68];
    __shared__ float Ks[BK][68];
    __shared__ float Vs[BK][68];
    __shared__ float Ss[BQ][33];

    int qb = blockIdx.x, h = blockIdx.y;
    int tid = threadIdx.x;
    int r = tid >> 2, g = tid & 3;
    int qg = qb * BQ + r;
    const float scale = 0.125f;

    for (int f = tid; f < BQ * 16; f += 256) {
        int rr = f >> 4, c4 = f & 15;
        *(float4*)&Qs[rr][c4 * 4] =
            *(const float4*)(Q + (long)(qb * BQ + rr) * HID + h * HDIM + c4 * 4);
    }

    float m_i = -1e30f, l_i = 0.f;
    float4 o4[4];
    #pragma unroll
    for (int i = 0; i < 4; i++) o4[i] = make_float4(0.f, 0.f, 0.f, 0.f);

    int nkt = (qb + 1) * (BQ / BK);

    for (int kt = 0; kt < nkt; kt++) {
        __syncthreads();
        for (int f = tid; f < BK * 16; f += 256) {
            int rr = f >> 4, c4 = f & 15;
            long base = (long)(kt * BK + rr) * HID + h * HDIM + c4 * 4;
            *(float4*)&Ks[rr][c4 * 4] = *(const float4*)(K + base);
            *(float4*)&Vs[rr][c4 * 4] = *(const float4*)(V + base);
        }
        __syncthreads();

        float sacc[8];
        #pragma unroll
        for (int kk = 0; kk < 8; kk++) sacc[kk] = 0.f;
        const float4* qrow = (const float4*)&Qs[r][0];
        #pragma unroll 4
        for (int d4 = 0; d4 < 16; d4++) {
            float4 qv = qrow[d4];
            #pragma unroll
            for (int kk = 0; kk < 8; kk++) {
                float4 kv = *(const float4*)&Ks[g * 8 + kk][d4 * 4];
                sacc[kk] += qv.x * kv.x + qv.y * kv.y + qv.z * kv.z + qv.w * kv.w;
            }
        }
        #pragma unroll
        for (int kk = 0; kk < 8; kk++) {
            int k = g * 8 + kk;
            int kg = kt * BK + k;
            float v = sacc[kk] * scale;
            if (kg > qg) v = -1e30f;
            Ss[r][k] = v;
        }
        __syncthreads();

        float m_new = m_i;
        #pragma unroll
        for (int k = 0; k < BK; k++) m_new = fmaxf(m_new, Ss[r][k]);
        float alpha = __expf(m_i - m_new);
        l_i *= alpha;
        #pragma unroll
        for (int i = 0; i < 4; i++) {
            o4[i].x *= alpha; o4[i].y *= alpha; o4[i].z *= alpha; o4[i].w *= alpha;
        }
        #pragma unroll 4
        for (int k = 0; k < BK; k++) {
            float p = __expf(Ss[r][k] - m_new);
            l_i += p;
            const float4* vrow = (const float4*)&Vs[k][g * 16];
            #pragma unroll
            for (int i = 0; i < 4; i++) {
                float4 vv = vrow[i];
                o4[i].x += p * vv.x; o4[i].y += p * vv.y;
                o4[i].z += p * vv.z; o4[i].w += p * vv.w;
            }
        }
        m_i = m_new;
    }

    float inv = 1.0f / l_i;
    long obase = (long)qg * HID + h * HDIM + g * 16;
    float ov[16];
    #pragma unroll
    for (int i = 0; i < 4; i++) {
        ov[i * 4 + 0] = o4[i].x * inv; ov[i * 4 + 1] = o4[i].y * inv;
        ov[i * 4 + 2] = o4[i].z * inv; ov[i * 4 + 3] = o4[i].w * inv;
    }
    #pragma unroll
    for (int j = 0; j < 16; j += 2) {
        __nv_bfloat16 h0 = __float2bfloat16(ov[j]);
        __nv_bfloat16 h1 = __float2bfloat16(ov[j + 1]);
        __nv_bfloat162 hp; hp.x = h0; hp.y = h1;
        __nv_bfloat162 lp;
        lp.x = __float2bfloat16(ov[j]     - __bfloat162float(h0));
        lp.y = __float2bfloat16(ov[j + 1] - __bfloat162float(h1));
        *(__nv_bfloat162*)(Oh + obase + j) = hp;
        *(__nv_bfloat162*)(Ol + obase + j) = lp;
    }
}

// ======================= orchestration =======================
extern "C" void kernel_launch(void* const* d_in, const int* in_sizes, int n_in,
                              void* d_out, int out_size) {
    const float* emb = (const float*)d_in[0];
    const float* Wq = (const float*)d_in[2];
    const float* Wk = (const float*)d_in[3];
    const float* Wv = (const float*)d_in[4];
    const float* Wo = (const float*)d_in[5];
    const float* bo = (const float*)d_in[6];
    const float* W1 = (const float*)d_in[7];
    const float* W2 = (const float*)d_in[8];
    const float* b2 = (const float*)d_in[9];
    const float* g1 = (const float*)d_in[10];
    const float* g2 = (const float*)d_in[11];
    const float* gf = (const float*)d_in[12];
    float* out = (float*)d_out;

    float *px, *pq, *pk, *pv;
    __nv_bfloat16 *phh, *phl, *pch, *pcl, *pmh, *pml;
    __nv_bfloat16 *wqh, *wql, *wkh, *wkl, *wvh, *wvl, *woh, *wol, *w1h, *w1l, *w2h, *w2l;
    cudaGetSymbolAddress((void**)&px,  g_x);
    cudaGetSymbolAddress((void**)&pq,  g_q);
    cudaGetSymbolAddress((void**)&pk,  g_k);
    cudaGetSymbolAddress((void**)&pv,  g_v);
    cudaGetSymbolAddress((void**)&phh, g_hh);
    cudaGetSymbolAddress((void**)&phl, g_hl);
    cudaGetSymbolAddress((void**)&pch, g_ctxh);
    cudaGetSymbolAddress((void**)&pcl, g_ctxl);
    cudaGetSymbolAddress((void**)&pmh, g_midh);
    cudaGetSymbolAddress((void**)&pml, g_midl);
    cudaGetSymbolAddress((void**)&wqh, g_wqt_h); cudaGetSymbolAddress((void**)&wql, g_wqt_l);
    cudaGetSymbolAddress((void**)&wkh, g_wkt_h); cudaGetSymbolAddress((void**)&wkl, g_wkt_l);
    cudaGetSymbolAddress((void**)&wvh, g_wvt_h); cudaGetSymbolAddress((void**)&wvl, g_wvt_l);
    cudaGetSymbolAddress((void**)&woh, g_wot_h); cudaGetSymbolAddress((void**)&wol, g_wot_l);
    cudaGetSymbolAddress((void**)&w1h, g_w1t_h); cudaGetSymbolAddress((void**)&w1l, g_w1t_l);
    cudaGetSymbolAddress((void**)&w2h, g_w2t_h); cudaGetSymbolAddress((void**)&w2l, g_w2t_l);

    cudaFuncSetAttribute(gemm_mma_kernel<0>, cudaFuncAttributeMaxDynamicSharedMemorySize, GSM_TOTAL);
    cudaFuncSetAttribute(gemm_mma_kernel<1>, cudaFuncAttributeMaxDynamicSharedMemorySize, GSM_TOTAL);
    cudaFuncSetAttribute(gemm_mma_kernel<2>, cudaFuncAttributeMaxDynamicSharedMemorySize, GSM_TOTAL);

    // x = inputs_embeds
    {
        int n4 = SEQ * HID / 4;
        copy_kernel<<<(n4 + 255) / 256, 256>>>((const float4*)emb, (float4*)px, n4);
    }

    // weight transpose+split
    {
        dim3 b(32, 8);
        dim3 gHH(HID / 32, HID / 32);
        dim3 gW1(ISZ / 32, HID / 32);
        dim3 gW2(HID / 32, ISZ / 32);
        for (int l = 0; l < NLAYER; l++) {
            long oHH = (long)l * HID * HID, oHI = (long)l * HID * ISZ;
            wsplit_kernel<<<gHH, b>>>(Wq + oHH, wqh + oHH, wql + oHH, HID, HID);
            wsplit_kernel<<<gHH, b>>>(Wk + oHH, wkh + oHH, wkl + oHH, HID, HID);
            wsplit_kernel<<<gHH, b>>>(Wv + oHH, wvh + oHH, wvl + oHH, HID, HID);
            wsplit_kernel<<<gHH, b>>>(Wo + oHH, woh + oHH, wol + oHH, HID, HID);
            wsplit_kernel<<<gW1, b>>>(W1 + oHI, w1h + oHI, w1l + oHI, HID, ISZ);
            wsplit_kernel<<<gW2, b>>>(W2 + oHI, w2h + oHI, w2l + oHI, ISZ, HID);
        }
    }

    dim3 gHH(HID / 128, SEQ / 128);
    dim3 gHI(ISZ / 128, SEQ / 128);
    dim3 gAttn(SEQ / 64, NHEAD);

    for (int l = 0; l < NLAYER; l++) {
        long oHH = (long)l * HID * HID, oHI = (long)l * HID * ISZ;

        // attention block
        ln_kernel<1><<<SEQ, 256>>>(px, g1 + l * HID, nullptr, phh, phl);
        gemm_mma_kernel<0><<<gHH, 256, GSM_TOTAL>>>(phh, phl, wqh + oHH, wql + oHH,
            nullptr, nullptr, pq, nullptr, nullptr, SEQ, HID, HID);
        gemm_mma_kernel<0><<<gHH, 256, GSM_TOTAL>>>(phh, phl, wkh + oHH, wkl + oHH,
            nullptr, nullptr, pk, nullptr, nullptr, SEQ, HID, HID);
        gemm_mma_kernel<0><<<gHH, 256, GSM_TOTAL>>>(phh, phl, wvh + oHH, wvl + oHH,
            nullptr, nullptr, pv, nullptr, nullptr, SEQ, HID, HID);
        attn_kernel<<<gAttn, 256>>>(pq, pk, pv, pch, pcl);
        // x = x + ctx @ Wo + bo
        gemm_mma_kernel<1><<<gHH, 256, GSM_TOTAL>>>(pch, pcl, woh + oHH, wol + oHH,
            bo + l * HID, px, px, nullptr, nullptr, SEQ, HID, HID);

        // MLP block
        ln_kernel<1><<<SEQ, 256>>>(px, g2 + l * HID, nullptr, phh, phl);
        gemm_mma_kernel<2><<<gHI, 256, GSM_TOTAL>>>(phh, phl, w1h + oHI, w1l + oHI,
            nullptr, nullptr, nullptr, pmh, pml, SEQ, ISZ, HID);
        // x = x + mid @ W2 + b2
        gemm_mma_kernel<1><<<gHH, 256, GSM_TOTAL>>>(pmh, pml, w2h + oHI, w2l + oHI,
            b2 + l * HID, px, px, nullptr, nullptr, SEQ, HID, ISZ);
    }

    ln_kernel<0><<<SEQ, 256>>>(px, gf, out, nullptr, nullptr);
}